// round 1
// baseline (speedup 1.0000x reference)
#include <cuda_runtime.h>
#include <math.h>

#define NN   30000
#define FF   500
#define HID  16
#define OUTC 3
#define EE   960000

// ---------------- scratch (device globals; no allocation allowed) ----------------
__device__ float g_hfeat[NN * HID];   // conv+maxpool output
__device__ float g_deg[NN];
__device__ float g_dinv[NN];
__device__ float g_t1[NN * HID];      // hfeat @ gcn1_w
__device__ float g_agg1[NN * HID];    // aggregated gcn1
__device__ float g_t2[NN * 4];        // relu(agg1+b1) @ gcn2_w  (padded to 4)
__device__ float g_agg2[NN * 4];      // aggregated gcn2

// ---------------- fused conv1 -> relu -> conv2 -> relu -> maxpool ----------------
// one block per node, 128 threads
__global__ void __launch_bounds__(128) conv_kernel(
    const float* __restrict__ x,
    const float* __restrict__ w1, const float* __restrict__ b1,
    const float* __restrict__ w2, const float* __restrict__ b2)
{
    __shared__ float sx[FF + 2];
    __shared__ float sh1[HID][FF + 2];
    __shared__ float sw1[HID * 3];
    __shared__ float sb1[HID];
    __shared__ float sw2[HID * HID * 3];
    __shared__ float sb2[HID];

    const int node = blockIdx.x;
    const int t = threadIdx.x;

    // stage weights + input row
    for (int i = t; i < HID * 3; i += 128) sw1[i] = w1[i];
    for (int i = t; i < HID * HID * 3; i += 128) sw2[i] = w2[i];
    if (t < HID) { sb1[t] = b1[t]; sb2[t] = b2[t]; }
    const float* xr = x + (size_t)node * FF;
    for (int p = t; p < FF; p += 128) sx[p + 1] = xr[p];
    if (t == 0) { sx[0] = 0.f; sx[FF + 1] = 0.f; }
    __syncthreads();

    // conv1 (in-channels = 1) + relu, write with zero halo for conv2's padding
    for (int idx = t; idx < HID * FF; idx += 128) {
        int i = idx / FF;
        int p = idx - i * FF;
        float v = sb1[i]
                + sw1[i * 3 + 0] * sx[p]
                + sw1[i * 3 + 1] * sx[p + 1]
                + sw1[i * 3 + 2] * sx[p + 2];
        sh1[i][p + 1] = fmaxf(v, 0.f);
    }
    if (t < HID) { sh1[t][0] = 0.f; sh1[t][FF + 1] = 0.f; }
    __syncthreads();

    // conv2 + relu + running max. positions t, t+128, t+256, t+384 per thread.
    float vmax[HID];
#pragma unroll
    for (int o = 0; o < HID; o++) vmax[o] = 0.f;   // relu'd values are >= 0

    {
        float acc[HID][4];
#pragma unroll
        for (int o = 0; o < HID; o++)
#pragma unroll
            for (int j = 0; j < 4; j++) acc[o][j] = sb2[o];

        for (int i = 0; i < HID; i++) {         // rolled: keeps SASS small
            float a[4][3];
#pragma unroll
            for (int j = 0; j < 4; j++) {
                int p = t + j * 128;
                if (p >= FF) p = 0;             // clamp; lane result discarded
                a[j][0] = sh1[i][p];
                a[j][1] = sh1[i][p + 1];
                a[j][2] = sh1[i][p + 2];
            }
#pragma unroll
            for (int o = 0; o < HID; o++) {
                float u0 = sw2[(o * HID + i) * 3 + 0];
                float u1 = sw2[(o * HID + i) * 3 + 1];
                float u2 = sw2[(o * HID + i) * 3 + 2];
#pragma unroll
                for (int j = 0; j < 4; j++)
                    acc[o][j] = fmaf(u0, a[j][0],
                                fmaf(u1, a[j][1],
                                fmaf(u2, a[j][2], acc[o][j])));
            }
        }
#pragma unroll
        for (int o = 0; o < HID; o++)
#pragma unroll
            for (int j = 0; j < 4; j++)
                if (t + j * 128 < FF) vmax[o] = fmaxf(vmax[o], acc[o][j]);
    }

    // block max-reduction (reuse sh1 storage)
    __syncthreads();
    float* red = &sh1[0][0];
#pragma unroll
    for (int o = 0; o < HID; o++) red[t * HID + o] = vmax[o];
    __syncthreads();
    for (int s = 64; s > 0; s >>= 1) {
        if (t < s) {
#pragma unroll
            for (int o = 0; o < HID; o++)
                red[t * HID + o] = fmaxf(red[t * HID + o], red[(t + s) * HID + o]);
        }
        __syncthreads();
    }
    if (t < HID) g_hfeat[node * HID + t] = red[t];
}

// ---------------- GCN support kernels ----------------
__global__ void init_deg_kernel() {
    int i = blockIdx.x * blockDim.x + threadIdx.x;
    if (i < NN) g_deg[i] = 1.0f;               // self loop
}

__global__ void count_deg_kernel(const int* __restrict__ ei) {
    int e = blockIdx.x * blockDim.x + threadIdx.x;
    if (e < EE) atomicAdd(&g_deg[ei[EE + e]], 1.0f);
}

__global__ void dinv_kernel() {
    int i = blockIdx.x * blockDim.x + threadIdx.x;
    if (i < NN) g_dinv[i] = rsqrtf(g_deg[i]);
}

// t1 = hfeat @ gcn1_w ; agg1 init = self-loop message t1[n]*dinv[n]^2
__global__ void gcn1_lin_kernel(const float* __restrict__ w) {
    int gid = blockIdx.x * blockDim.x + threadIdx.x;
    if (gid >= NN * HID) return;
    int n = gid >> 4;
    int o = gid & 15;
    const float* h = g_hfeat + n * HID;
    float s = 0.f;
#pragma unroll
    for (int i = 0; i < HID; i++) s = fmaf(h[i], w[i * HID + o], s);
    g_t1[gid] = s;
    float di = g_dinv[n];
    g_agg1[gid] = s * di * di;
}

__global__ void scatter1_kernel(const int* __restrict__ ei) {
    int e = blockIdx.x * blockDim.x + threadIdx.x;
    if (e >= EE) return;
    int s = ei[e];
    int d = ei[EE + e];
    float norm = g_dinv[s] * g_dinv[d];
    const float4* ts = (const float4*)(g_t1 + s * HID);
    float* out = g_agg1 + d * HID;
#pragma unroll
    for (int q = 0; q < 4; q++) {
        float4 v = ts[q];
        atomicAdd(out + q * 4 + 0, v.x * norm);
        atomicAdd(out + q * 4 + 1, v.y * norm);
        atomicAdd(out + q * 4 + 2, v.z * norm);
        atomicAdd(out + q * 4 + 3, v.w * norm);
    }
}

// hg = relu(agg1 + b1); t2 = hg @ gcn2_w; agg2 init = self-loop message
__global__ void gcn2_lin_kernel(const float* __restrict__ b1,
                                const float* __restrict__ w2g) {
    int n = blockIdx.x * blockDim.x + threadIdx.x;
    if (n >= NN) return;
    float hg[HID];
#pragma unroll
    for (int o = 0; o < HID; o++)
        hg[o] = fmaxf(g_agg1[n * HID + o] + b1[o], 0.f);
    float di = g_dinv[n];
    float d2 = di * di;
#pragma unroll
    for (int j = 0; j < OUTC; j++) {
        float s = 0.f;
#pragma unroll
        for (int o = 0; o < HID; o++) s = fmaf(hg[o], w2g[o * OUTC + j], s);
        g_t2[n * 4 + j] = s;
        g_agg2[n * 4 + j] = s * d2;
    }
    g_t2[n * 4 + 3] = 0.f;
    g_agg2[n * 4 + 3] = 0.f;
}

__global__ void scatter2_kernel(const int* __restrict__ ei) {
    int e = blockIdx.x * blockDim.x + threadIdx.x;
    if (e >= EE) return;
    int s = ei[e];
    int d = ei[EE + e];
    float norm = g_dinv[s] * g_dinv[d];
    float4 v = *(const float4*)(g_t2 + s * 4);
    atomicAdd(&g_agg2[d * 4 + 0], v.x * norm);
    atomicAdd(&g_agg2[d * 4 + 1], v.y * norm);
    atomicAdd(&g_agg2[d * 4 + 2], v.z * norm);
}

__global__ void final_kernel(const float* __restrict__ b2g,
                             float* __restrict__ out) {
    int n = blockIdx.x * blockDim.x + threadIdx.x;
    if (n >= NN) return;
    float v0 = g_agg2[n * 4 + 0] + b2g[0];
    float v1 = g_agg2[n * 4 + 1] + b2g[1];
    float v2 = g_agg2[n * 4 + 2] + b2g[2];
    float m = fmaxf(v0, fmaxf(v1, v2));
    float lse = logf(expf(v0 - m) + expf(v1 - m) + expf(v2 - m)) + m;
    out[n * 3 + 0] = v0 - m - lse + m - m;  // keep simple: v - (m + lse_rel)
    out[n * 3 + 0] = v0 - (m + lse - m);    // (overwritten below for clarity)
    float z = m + (lse - m);
    out[n * 3 + 0] = v0 - z;
    out[n * 3 + 1] = v1 - z;
    out[n * 3 + 2] = v2 - z;
}

// ---------------- launch ----------------
extern "C" void kernel_launch(void* const* d_in, const int* in_sizes, int n_in,
                              void* d_out, int out_size)
{
    const float* x   = (const float*)d_in[0];
    const float* c1w = (const float*)d_in[1];
    const float* c1b = (const float*)d_in[2];
    const float* c2w = (const float*)d_in[3];
    const float* c2b = (const float*)d_in[4];
    const float* g1w = (const float*)d_in[5];
    const float* g1b = (const float*)d_in[6];
    const float* g2w = (const float*)d_in[7];
    const float* g2b = (const float*)d_in[8];
    const int*   ei  = (const int*)d_in[9];
    float* out = (float*)d_out;

    conv_kernel<<<NN, 128>>>(x, c1w, c1b, c2w, c2b);

    init_deg_kernel<<<(NN + 255) / 256, 256>>>();
    count_deg_kernel<<<(EE + 255) / 256, 256>>>(ei);
    dinv_kernel<<<(NN + 255) / 256, 256>>>();

    gcn1_lin_kernel<<<(NN * HID + 127) / 128, 128>>>(g1w);
    scatter1_kernel<<<(EE + 255) / 256, 256>>>(ei);

    gcn2_lin_kernel<<<(NN + 255) / 256, 256>>>(g1b, g2w);
    scatter2_kernel<<<(EE + 255) / 256, 256>>>(ei);

    final_kernel<<<(NN + 255) / 256, 256>>>(g2b, out);
}

// round 2
// speedup vs baseline: 1.0890x; 1.0890x over previous
#include <cuda_runtime.h>
#include <math.h>

#define NN   30000
#define FF   500
#define HID  16
#define OUTC 3
#define EE   960000

typedef unsigned long long ull;

// ---------------- packed f32x2 helpers (sm_103a) ----------------
__device__ __forceinline__ ull pk2(float lo, float hi) {
    ull r; asm("mov.b64 %0, {%1,%2};" : "=l"(r) : "f"(lo), "f"(hi)); return r;
}
__device__ __forceinline__ void upk2(ull v, float& lo, float& hi) {
    asm("mov.b64 {%0,%1}, %2;" : "=f"(lo), "=f"(hi) : "l"(v));
}
__device__ __forceinline__ ull fma2(ull a, ull b, ull c) {
    ull d; asm("fma.rn.f32x2 %0, %1, %2, %3;" : "=l"(d) : "l"(a), "l"(b), "l"(c)); return d;
}
__device__ __forceinline__ void red_add_v4(float* p, float a, float b, float c, float d) {
    asm volatile("red.global.add.v4.f32 [%0], {%1,%2,%3,%4};"
                 :: "l"(p), "f"(a), "f"(b), "f"(c), "f"(d) : "memory");
}

// ---------------- scratch (device globals) ----------------
__device__ float g_hfeat[NN * HID];
__device__ float g_deg[NN];
__device__ float g_dinv[NN];
__device__ float g_t1[NN * HID];
__device__ float g_agg1[NN * HID];
__device__ float g_t2[NN * 4];
__device__ float g_agg2[NN * 4];

// ---------------- fused conv1 -> relu -> conv2 -> relu -> maxpool ----------------
__global__ void __launch_bounds__(128) conv_kernel(
    const float* __restrict__ x,
    const float* __restrict__ w1, const float* __restrict__ b1,
    const float* __restrict__ w2, const float* __restrict__ b2)
{
    __shared__ float sx[FF + 2];
    __shared__ float sh1[HID][FF + 2];
    __shared__ float sw1[HID * 3];
    __shared__ float sb1[HID];
    __shared__ ull   sw2d[HID * HID * 3];   // duplicated-pair weights for FFMA2
    __shared__ float sb2[HID];

    const int node = blockIdx.x;
    const int t = threadIdx.x;

    for (int i = t; i < HID * 3; i += 128) sw1[i] = w1[i];
    for (int i = t; i < HID * HID * 3; i += 128) { float w = w2[i]; sw2d[i] = pk2(w, w); }
    if (t < HID) { sb1[t] = b1[t]; sb2[t] = b2[t]; }
    const float* xr = x + (size_t)node * FF;
    for (int p = t; p < FF; p += 128) sx[p + 1] = xr[p];
    if (t == 0) { sx[0] = 0.f; sx[FF + 1] = 0.f; }
    __syncthreads();

    // conv1 + relu, zero halo
    for (int idx = t; idx < HID * FF; idx += 128) {
        int i = idx / FF;
        int p = idx - i * FF;
        float v = sb1[i]
                + sw1[i * 3 + 0] * sx[p]
                + sw1[i * 3 + 1] * sx[p + 1]
                + sw1[i * 3 + 2] * sx[p + 2];
        sh1[i][p + 1] = fmaxf(v, 0.f);
    }
    if (t < HID) { sh1[t][0] = 0.f; sh1[t][FF + 1] = 0.f; }
    __syncthreads();

    // conv2 with packed f32x2 accumulators: positions (t, t+128) and (t+256, t+384)
    ull acc2[HID][2];
#pragma unroll
    for (int o = 0; o < HID; o++) {
        float bo = sb2[o];
        ull b2p = pk2(bo, bo);
        acc2[o][0] = b2p;
        acc2[o][1] = b2p;
    }

    for (int i = 0; i < HID; i++) {
        float a[4][3];
#pragma unroll
        for (int j = 0; j < 4; j++) {
            int p = t + j * 128;
            if (p >= FF) p = 0;              // clamped lanes discarded later
            a[j][0] = sh1[i][p];
            a[j][1] = sh1[i][p + 1];
            a[j][2] = sh1[i][p + 2];
        }
        ull a2[2][3];
#pragma unroll
        for (int q = 0; q < 2; q++) {
#pragma unroll
            for (int k = 0; k < 3; k++)
                a2[q][k] = pk2(a[2 * q][k], a[2 * q + 1][k]);
        }
#pragma unroll
        for (int o = 0; o < HID; o++) {
            const ull* wp = &sw2d[(o * HID + i) * 3];
            ull u0 = wp[0], u1 = wp[1], u2 = wp[2];
#pragma unroll
            for (int q = 0; q < 2; q++)
                acc2[o][q] = fma2(u0, a2[q][0],
                             fma2(u1, a2[q][1],
                             fma2(u2, a2[q][2], acc2[o][q])));
        }
    }

    // relu + per-thread max over valid positions
    float vmax[HID];
#pragma unroll
    for (int o = 0; o < HID; o++) {
        float v0, v1, v2, v3;
        upk2(acc2[o][0], v0, v1);
        upk2(acc2[o][1], v2, v3);
        float m = 0.f;                       // relu floor
        if (t            < FF) m = fmaxf(m, v0);
        if (t + 128      < FF) m = fmaxf(m, v1);
        if (t + 256      < FF) m = fmaxf(m, v2);
        if (t + 384      < FF) m = fmaxf(m, v3);
        vmax[o] = m;
    }

    // block max-reduction (reuse sh1)
    __syncthreads();
    float* red = &sh1[0][0];
#pragma unroll
    for (int o = 0; o < HID; o++) red[t * HID + o] = vmax[o];
    __syncthreads();
    for (int s = 64; s > 0; s >>= 1) {
        if (t < s) {
#pragma unroll
            for (int o = 0; o < HID; o++)
                red[t * HID + o] = fmaxf(red[t * HID + o], red[(t + s) * HID + o]);
        }
        __syncthreads();
    }
    if (t < HID) g_hfeat[node * HID + t] = red[t];
}

// ---------------- GCN support kernels ----------------
__global__ void init_deg_kernel() {
    int i = blockIdx.x * blockDim.x + threadIdx.x;
    if (i < NN) g_deg[i] = 1.0f;             // self loop
}

__global__ void count_deg_kernel(const int* __restrict__ ei) {
    int e = blockIdx.x * blockDim.x + threadIdx.x;
    if (e < EE) atomicAdd(&g_deg[ei[EE + e]], 1.0f);
}

__global__ void dinv_kernel() {
    int i = blockIdx.x * blockDim.x + threadIdx.x;
    if (i < NN) g_dinv[i] = rsqrtf(g_deg[i]);
}

__global__ void gcn1_lin_kernel(const float* __restrict__ w) {
    int gid = blockIdx.x * blockDim.x + threadIdx.x;
    if (gid >= NN * HID) return;
    int n = gid >> 4;
    int o = gid & 15;
    const float* h = g_hfeat + n * HID;
    float s = 0.f;
#pragma unroll
    for (int i = 0; i < HID; i++) s = fmaf(h[i], w[i * HID + o], s);
    g_t1[gid] = s;
    float di = g_dinv[n];
    g_agg1[gid] = s * di * di;               // self-loop term
}

__global__ void scatter1_kernel(const int* __restrict__ ei) {
    int e = blockIdx.x * blockDim.x + threadIdx.x;
    if (e >= EE) return;
    int s = ei[e];
    int d = ei[EE + e];
    float norm = g_dinv[s] * g_dinv[d];
    const float4* ts = (const float4*)(g_t1 + s * HID);
    float* out = g_agg1 + d * HID;
#pragma unroll
    for (int q = 0; q < 4; q++) {
        float4 v = ts[q];
        red_add_v4(out + q * 4, v.x * norm, v.y * norm, v.z * norm, v.w * norm);
    }
}

__global__ void gcn2_lin_kernel(const float* __restrict__ b1,
                                const float* __restrict__ w2g) {
    int n = blockIdx.x * blockDim.x + threadIdx.x;
    if (n >= NN) return;
    float hg[HID];
#pragma unroll
    for (int o = 0; o < HID; o++)
        hg[o] = fmaxf(g_agg1[n * HID + o] + b1[o], 0.f);
    float di = g_dinv[n];
    float d2 = di * di;
#pragma unroll
    for (int j = 0; j < OUTC; j++) {
        float s = 0.f;
#pragma unroll
        for (int o = 0; o < HID; o++) s = fmaf(hg[o], w2g[o * OUTC + j], s);
        g_t2[n * 4 + j] = s;
        g_agg2[n * 4 + j] = s * d2;
    }
    g_t2[n * 4 + 3] = 0.f;
    g_agg2[n * 4 + 3] = 0.f;
}

__global__ void scatter2_kernel(const int* __restrict__ ei) {
    int e = blockIdx.x * blockDim.x + threadIdx.x;
    if (e >= EE) return;
    int s = ei[e];
    int d = ei[EE + e];
    float norm = g_dinv[s] * g_dinv[d];
    float4 v = *(const float4*)(g_t2 + s * 4);
    red_add_v4(g_agg2 + d * 4, v.x * norm, v.y * norm, v.z * norm, 0.f);
}

__global__ void final_kernel(const float* __restrict__ b2g,
                             float* __restrict__ out) {
    int n = blockIdx.x * blockDim.x + threadIdx.x;
    if (n >= NN) return;
    float v0 = g_agg2[n * 4 + 0] + b2g[0];
    float v1 = g_agg2[n * 4 + 1] + b2g[1];
    float v2 = g_agg2[n * 4 + 2] + b2g[2];
    float m = fmaxf(v0, fmaxf(v1, v2));
    float z = m + logf(expf(v0 - m) + expf(v1 - m) + expf(v2 - m));
    out[n * 3 + 0] = v0 - z;
    out[n * 3 + 1] = v1 - z;
    out[n * 3 + 2] = v2 - z;
}

// ---------------- launch ----------------
extern "C" void kernel_launch(void* const* d_in, const int* in_sizes, int n_in,
                              void* d_out, int out_size)
{
    const float* x   = (const float*)d_in[0];
    const float* c1w = (const float*)d_in[1];
    const float* c1b = (const float*)d_in[2];
    const float* c2w = (const float*)d_in[3];
    const float* c2b = (const float*)d_in[4];
    const float* g1w = (const float*)d_in[5];
    const float* g1b = (const float*)d_in[6];
    const float* g2w = (const float*)d_in[7];
    const float* g2b = (const float*)d_in[8];
    const int*   ei  = (const int*)d_in[9];
    float* out = (float*)d_out;

    conv_kernel<<<NN, 128>>>(x, c1w, c1b, c2w, c2b);

    init_deg_kernel<<<(NN + 255) / 256, 256>>>();
    count_deg_kernel<<<(EE + 255) / 256, 256>>>(ei);
    dinv_kernel<<<(NN + 255) / 256, 256>>>();

    gcn1_lin_kernel<<<(NN * HID + 127) / 128, 128>>>(g1w);
    scatter1_kernel<<<(EE + 255) / 256, 256>>>(ei);

    gcn2_lin_kernel<<<(NN + 255) / 256, 256>>>(g1b, g2w);
    scatter2_kernel<<<(EE + 255) / 256, 256>>>(ei);

    final_kernel<<<(NN + 255) / 256, 256>>>(g2b, out);
}

// round 3
// speedup vs baseline: 1.2780x; 1.1736x over previous
#include <cuda_runtime.h>
#include <math.h>

#define NN   30000
#define FF   500
#define HID  16
#define OUTC 3
#define EE   960000

#define ROW  520              // sh1 row stride (floats): 500+2 halo, padded for OOB reads, 16B-aligned

typedef unsigned long long ull;

// ---------------- packed f32x2 helpers (sm_103a) ----------------
__device__ __forceinline__ ull pk2(float lo, float hi) {
    ull r; asm("mov.b64 %0, {%1,%2};" : "=l"(r) : "f"(lo), "f"(hi)); return r;
}
__device__ __forceinline__ void upk2(ull v, float& lo, float& hi) {
    asm("mov.b64 {%0,%1}, %2;" : "=f"(lo), "=f"(hi) : "l"(v));
}
__device__ __forceinline__ ull fma2(ull a, ull b, ull c) {
    ull d; asm("fma.rn.f32x2 %0, %1, %2, %3;" : "=l"(d) : "l"(a), "l"(b), "l"(c)); return d;
}
__device__ __forceinline__ void red_add_v4(float* p, float a, float b, float c, float d) {
    asm volatile("red.global.add.v4.f32 [%0], {%1,%2,%3,%4};"
                 :: "l"(p), "f"(a), "f"(b), "f"(c), "f"(d) : "memory");
}

// ---------------- scratch (device globals) ----------------
__device__ float g_hfeat[NN * HID];
__device__ float g_deg[NN];
__device__ float g_dinv[NN];
__device__ float g_t1[NN * HID];
__device__ float g_agg1[NN * HID];
__device__ float g_t2[NN * 4];
__device__ float g_agg2[NN * 4];

// ---------------- fused conv1 -> relu -> conv2 -> relu -> maxpool ----------------
// 128 threads: t<64 computes outputs 0..7, t>=64 outputs 8..15.
// Each thread owns 8 contiguous positions [8*pt, 8*pt+8), pt = t & 63.
__global__ void __launch_bounds__(128) conv_kernel(
    const float* __restrict__ x,
    const float* __restrict__ w1, const float* __restrict__ b1,
    const float* __restrict__ w2, const float* __restrict__ b2)
{
    __shared__ float sx[FF + 2];
    __shared__ __align__(16) float sh1[HID][ROW];
    __shared__ float sw1[HID * 3];
    __shared__ float sb1[HID];
    __shared__ __align__(16) ull sw2p[HID * HID * 3];  // [i][o][tap], duplicated pairs
    __shared__ float sb2[HID];
    __shared__ float sred[4][8];                       // per-warp max partials

    const int node = blockIdx.x;
    const int t = threadIdx.x;

    // stage weights: sw2p[(i*16+o)*3+k] = dup-pair of w2[(o*16+i)*3+k]
    for (int idx = t; idx < HID * HID * 3; idx += 128) {
        int k = idx % 3;
        int oi = idx / 3;
        int o = oi & 15;
        int i = oi >> 4;
        float w = w2[(o * HID + i) * 3 + k];
        sw2p[(i * HID + o) * 3 + k] = pk2(w, w);
    }
    for (int i = t; i < HID * 3; i += 128) sw1[i] = w1[i];
    if (t < HID) { sb1[t] = b1[t]; sb2[t] = b2[t]; }
    const float* xr = x + (size_t)node * FF;
    for (int p = t; p < FF; p += 128) sx[p + 1] = xr[p];
    if (t == 0) { sx[0] = 0.f; sx[FF + 1] = 0.f; }
    __syncthreads();

    // conv1 + relu into sh1 (halo index +1); zero-pad [0] and [501..ROW)
    for (int idx = t; idx < HID * FF; idx += 128) {
        int i = idx / FF;
        int p = idx - i * FF;
        float v = sb1[i]
                + sw1[i * 3 + 0] * sx[p]
                + sw1[i * 3 + 1] * sx[p + 1]
                + sw1[i * 3 + 2] * sx[p + 2];
        sh1[i][p + 1] = fmaxf(v, 0.f);
    }
    // zero padding: indices 0 and [FF+1, ROW) per row -> 16*(1 + 19) = 320 stores
    for (int idx = t; idx < HID * (ROW - FF - 1 + 1); idx += 128) {
        int per = ROW - FF;                 // 20 pad slots per row (index 0 + 501..519)
        int i = idx / per;
        int j = idx % per;
        if (i < HID) sh1[i][j == 0 ? 0 : FF + j] = 0.f;
    }
    __syncthreads();

    const int ohalf = t >> 6;               // 0 or 1
    const int pt = t & 63;
    const int pbase = pt * 8;

    // 8 outputs x 4 position-pairs, packed accumulators
    ull acc[8][4];
#pragma unroll
    for (int o = 0; o < 8; o++) {
        float bo = sb2[ohalf * 8 + o];
        ull bp = pk2(bo, bo);
#pragma unroll
        for (int q = 0; q < 4; q++) acc[o][q] = bp;
    }

    for (int i = 0; i < HID; i++) {
        // activations: 12 floats = 3 x LDS.128
        const float4* frow = (const float4*)&sh1[i][pbase];
        float4 f0 = frow[0], f1 = frow[1], f2 = frow[2];
        float f[12] = { f0.x, f0.y, f0.z, f0.w, f1.x, f1.y, f1.z, f1.w,
                        f2.x, f2.y, f2.z, f2.w };
        ull pr[10];
#pragma unroll
        for (int m = 0; m < 10; m++) pr[m] = pk2(f[m], f[m + 1]);

        // weights: 24 ull contiguous = 12 x LDS.128
        const ulonglong2* wp =
            (const ulonglong2*)&sw2p[(i * HID + ohalf * 8) * 3];
        ull warr[24];
#pragma unroll
        for (int m = 0; m < 12; m++) {
            ulonglong2 v = wp[m];
            warr[2 * m] = v.x; warr[2 * m + 1] = v.y;
        }

#pragma unroll
        for (int o = 0; o < 8; o++) {
            ull u0 = warr[o * 3 + 0], u1 = warr[o * 3 + 1], u2 = warr[o * 3 + 2];
#pragma unroll
            for (int q = 0; q < 4; q++)
                acc[o][q] = fma2(u0, pr[2 * q + 0],
                            fma2(u1, pr[2 * q + 1],
                            fma2(u2, pr[2 * q + 2], acc[o][q])));
        }
    }

    // relu + per-thread max over valid positions
    float vmax[8];
#pragma unroll
    for (int o = 0; o < 8; o++) {
        float m = 0.f;                      // relu floor
#pragma unroll
        for (int q = 0; q < 4; q++) {
            float vlo, vhi;
            upk2(acc[o][q], vlo, vhi);
            if (pbase + 2 * q     < FF) m = fmaxf(m, vlo);
            if (pbase + 2 * q + 1 < FF) m = fmaxf(m, vhi);
        }
        vmax[o] = m;
    }

    // warp-level max reduction (all lanes same ohalf within a warp)
#pragma unroll
    for (int o = 0; o < 8; o++) {
#pragma unroll
        for (int s = 16; s > 0; s >>= 1)
            vmax[o] = fmaxf(vmax[o], __shfl_xor_sync(0xFFFFFFFFu, vmax[o], s));
    }
    const int warp = t >> 5;
    if ((t & 31) == 0) {
#pragma unroll
        for (int o = 0; o < 8; o++) sred[warp][o] = vmax[o];
    }
    __syncthreads();
    if (t < HID) {
        int o = t & 7;
        int base = (t >> 3) * 2;            // warps {0,1} for o<8, {2,3} for o>=8
        g_hfeat[node * HID + t] = fmaxf(sred[base][o], sred[base + 1][o]);
    }
}

// ---------------- GCN support kernels ----------------
__global__ void init_deg_kernel() {
    int i = blockIdx.x * blockDim.x + threadIdx.x;
    if (i < NN) g_deg[i] = 1.0f;             // self loop
}

__global__ void count_deg_kernel(const int* __restrict__ ei) {
    int e = blockIdx.x * blockDim.x + threadIdx.x;
    if (e < EE) atomicAdd(&g_deg[ei[EE + e]], 1.0f);
}

__global__ void dinv_kernel() {
    int i = blockIdx.x * blockDim.x + threadIdx.x;
    if (i < NN) g_dinv[i] = rsqrtf(g_deg[i]);
}

__global__ void gcn1_lin_kernel(const float* __restrict__ w) {
    int gid = blockIdx.x * blockDim.x + threadIdx.x;
    if (gid >= NN * HID) return;
    int n = gid >> 4;
    int o = gid & 15;
    const float* h = g_hfeat + n * HID;
    float s = 0.f;
#pragma unroll
    for (int i = 0; i < HID; i++) s = fmaf(h[i], w[i * HID + o], s);
    g_t1[gid] = s;
    float di = g_dinv[n];
    g_agg1[gid] = s * di * di;               // self-loop term
}

__global__ void scatter1_kernel(const int* __restrict__ ei) {
    int e = blockIdx.x * blockDim.x + threadIdx.x;
    if (e >= EE) return;
    int s = ei[e];
    int d = ei[EE + e];
    float norm = g_dinv[s] * g_dinv[d];
    const float4* ts = (const float4*)(g_t1 + s * HID);
    float* out = g_agg1 + d * HID;
#pragma unroll
    for (int q = 0; q < 4; q++) {
        float4 v = ts[q];
        red_add_v4(out + q * 4, v.x * norm, v.y * norm, v.z * norm, v.w * norm);
    }
}

__global__ void gcn2_lin_kernel(const float* __restrict__ b1,
                                const float* __restrict__ w2g) {
    int n = blockIdx.x * blockDim.x + threadIdx.x;
    if (n >= NN) return;
    float hg[HID];
#pragma unroll
    for (int o = 0; o < HID; o++)
        hg[o] = fmaxf(g_agg1[n * HID + o] + b1[o], 0.f);
    float di = g_dinv[n];
    float d2 = di * di;
#pragma unroll
    for (int j = 0; j < OUTC; j++) {
        float s = 0.f;
#pragma unroll
        for (int o = 0; o < HID; o++) s = fmaf(hg[o], w2g[o * OUTC + j], s);
        g_t2[n * 4 + j] = s;
        g_agg2[n * 4 + j] = s * d2;
    }
    g_t2[n * 4 + 3] = 0.f;
    g_agg2[n * 4 + 3] = 0.f;
}

__global__ void scatter2_kernel(const int* __restrict__ ei) {
    int e = blockIdx.x * blockDim.x + threadIdx.x;
    if (e >= EE) return;
    int s = ei[e];
    int d = ei[EE + e];
    float norm = g_dinv[s] * g_dinv[d];
    float4 v = *(const float4*)(g_t2 + s * 4);
    red_add_v4(g_agg2 + d * 4, v.x * norm, v.y * norm, v.z * norm, 0.f);
}

__global__ void final_kernel(const float* __restrict__ b2g,
                             float* __restrict__ out) {
    int n = blockIdx.x * blockDim.x + threadIdx.x;
    if (n >= NN) return;
    float v0 = g_agg2[n * 4 + 0] + b2g[0];
    float v1 = g_agg2[n * 4 + 1] + b2g[1];
    float v2 = g_agg2[n * 4 + 2] + b2g[2];
    float m = fmaxf(v0, fmaxf(v1, v2));
    float z = m + logf(expf(v0 - m) + expf(v1 - m) + expf(v2 - m));
    out[n * 3 + 0] = v0 - z;
    out[n * 3 + 1] = v1 - z;
    out[n * 3 + 2] = v2 - z;
}

// ---------------- launch ----------------
extern "C" void kernel_launch(void* const* d_in, const int* in_sizes, int n_in,
                              void* d_out, int out_size)
{
    const float* x   = (const float*)d_in[0];
    const float* c1w = (const float*)d_in[1];
    const float* c1b = (const float*)d_in[2];
    const float* c2w = (const float*)d_in[3];
    const float* c2b = (const float*)d_in[4];
    const float* g1w = (const float*)d_in[5];
    const float* g1b = (const float*)d_in[6];
    const float* g2w = (const float*)d_in[7];
    const float* g2b = (const float*)d_in[8];
    const int*   ei  = (const int*)d_in[9];
    float* out = (float*)d_out;

    conv_kernel<<<NN, 128>>>(x, c1w, c1b, c2w, c2b);

    init_deg_kernel<<<(NN + 255) / 256, 256>>>();
    count_deg_kernel<<<(EE + 255) / 256, 256>>>(ei);
    dinv_kernel<<<(NN + 255) / 256, 256>>>();

    gcn1_lin_kernel<<<(NN * HID + 127) / 128, 128>>>(g1w);
    scatter1_kernel<<<(EE + 255) / 256, 256>>>(ei);

    gcn2_lin_kernel<<<(NN + 255) / 256, 256>>>(g1b, g2w);
    scatter2_kernel<<<(EE + 255) / 256, 256>>>(ei);

    final_kernel<<<(NN + 255) / 256, 256>>>(g2b, out);
}